// round 14
// baseline (speedup 1.0000x reference)
#include <cuda_runtime.h>
#include <cuda_bf16.h>
#include <math.h>
#include <stdint.h>

// Geometry (fixed): B=4096, D=512, V=50000
#define DCONST 512
#define BQ     4096
#define VQ     50000
#define VPAD   50176          // 196 * 256
#define BM     128
#define BN     256
#define NCT    (VPAD / BN)    // 196 col tiles
#define BK     32             // bf16 -> 64 bytes per row-chunk
#define NKC    (DCONST / BK)  // 16 k-chunks
#define STAGES 3
#define A_BYTES 8192          // 128 rows x 64B
#define B_BYTES 16384         // 256 rows x 64B
#define STAGE_BYTES (A_BYTES + B_BYTES)     // 24576
#define GEMM_DSMEM (STAGES * STAGE_BYTES)   // 73728 (opt-in)
#define EPSF   1e-8f

// ---------------- scratch (device globals) ----------------
__device__ __align__(128) __nv_bfloat16 g_abf[(size_t)BQ * DCONST];    // 4 MB
__device__ __align__(128) __nv_bfloat16 g_vbf[(size_t)VPAD * DCONST];  // 51.2 MB
__device__ float  g_dpos[BQ];
__device__ float4 g_part[(size_t)BQ * NCT];
__device__ float  g_rowcost[BQ];

// ---------------- PTX helpers ----------------
__device__ __forceinline__ uint32_t smem_u32(const void* p) {
    uint32_t a;
    asm("{ .reg .u64 t; cvta.to.shared.u64 t, %1; cvt.u32.u64 %0, t; }" : "=r"(a) : "l"(p));
    return a;
}
__device__ __forceinline__ void cp16(uint32_t dst, const void* src) {
    asm volatile("cp.async.cg.shared.global [%0], [%1], 16;" :: "r"(dst), "l"(src) : "memory");
}
#define CP_COMMIT() asm volatile("cp.async.commit_group;" ::: "memory")
#define CP_WAIT(n)  asm volatile("cp.async.wait_group %0;" :: "n"(n) : "memory")

__device__ __forceinline__ void ldsm4(uint32_t (&r)[4], uint32_t addr) {
    asm volatile("ldmatrix.sync.aligned.m8n8.x4.shared.b16 {%0,%1,%2,%3}, [%4];"
        : "=r"(r[0]), "=r"(r[1]), "=r"(r[2]), "=r"(r[3]) : "r"(addr));
}
__device__ __forceinline__ void mma16816(float (&d)[4], const uint32_t (&a)[4],
                                         uint32_t b0, uint32_t b1) {
    asm volatile(
        "mma.sync.aligned.m16n8k16.row.col.f32.bf16.bf16.f32 "
        "{%0,%1,%2,%3}, {%4,%5,%6,%7}, {%8,%9}, {%0,%1,%2,%3};"
        : "+f"(d[0]), "+f"(d[1]), "+f"(d[2]), "+f"(d[3])
        : "r"(a[0]), "r"(a[1]), "r"(a[2]), "r"(a[3]), "r"(b0), "r"(b1));
}

// XOR swizzle of 16B chunk index within a 64B row (conflict-free for both
// cp.async stores and ldmatrix 8-lane phases)
__device__ __forceinline__ uint32_t swz(uint32_t r) {
    return (r & 3u) ^ ((r >> 2) & 1u);
}

// Top-2 merge, lower index wins ties (matches lax.top_k)
__device__ __forceinline__ void merge_top2(float &m1, int &i1, float &m2,
                                           float o1, int oi, float o2) {
    if (o1 > m1 || (o1 == m1 && oi < i1)) {
        m2 = fmaxf(m1, o2);
        m1 = o1;
        i1 = oi;
    } else {
        m2 = fmaxf(m2, o1);
    }
}

// ---------------- K1: row stats (d_pos) + normalized bf16 input ----------------
__global__ void k_rowstats_cvt(const float* __restrict__ inp,
                               const float* __restrict__ tgt) {
    const int row = blockIdx.x;
    const int t = threadIdx.x;  // 128
    const float4* ip = (const float4*)(inp + (size_t)row * DCONST);
    const float4* tp = (const float4*)(tgt + (size_t)row * DCONST);
    float4 a = ip[t];
    float4 b = tp[t];
    float ssi = a.x * a.x + a.y * a.y + a.z * a.z + a.w * a.w;
    float sst = b.x * b.x + b.y * b.y + b.z * b.z + b.w * b.w;
    float dot = a.x * b.x + a.y * b.y + a.z * b.z + a.w * b.w;
    #pragma unroll
    for (int off = 16; off; off >>= 1) {
        ssi += __shfl_xor_sync(0xffffffffu, ssi, off);
        sst += __shfl_xor_sync(0xffffffffu, sst, off);
        dot += __shfl_xor_sync(0xffffffffu, dot, off);
    }
    __shared__ float s1[4], s2[4], s3[4];
    __shared__ float s_rinv;
    int w = t >> 5;
    if ((t & 31) == 0) { s1[w] = ssi; s2[w] = sst; s3[w] = dot; }
    __syncthreads();
    if (t == 0) {
        float si = s1[0] + s1[1] + s1[2] + s1[3];
        float st = s2[0] + s2[1] + s2[2] + s2[3];
        float dd = s3[0] + s3[1] + s3[2] + s3[3];
        float ni = fmaxf(sqrtf(si), EPSF);
        float nt = fmaxf(sqrtf(st), EPSF);
        float sim = dd / (ni * nt);
        g_dpos[row] = sqrtf(fmaxf(2.f * (1.f - sim), 1e-12f));
        s_rinv = 1.f / ni;
    }
    __syncthreads();
    float rv = s_rinv;
    __nv_bfloat162 lo = __floats2bfloat162_rn(a.x * rv, a.y * rv);
    __nv_bfloat162 hi = __floats2bfloat162_rn(a.z * rv, a.w * rv);
    uint2 pk;
    pk.x = *(uint32_t*)&lo;
    pk.y = *(uint32_t*)&hi;
    *(uint2*)(g_abf + (size_t)row * DCONST + t * 4) = pk;
}

// ---------------- K2: normalized bf16 veclist (zero-padded to VPAD) ----------------
__global__ void k_cvt_v(const float* __restrict__ vl) {
    const int row = blockIdx.x;
    const int t = threadIdx.x;  // 128
    if (row >= VQ) {
        *(uint2*)(g_vbf + (size_t)row * DCONST + t * 4) = make_uint2(0u, 0u);
        return;
    }
    const float4* vp = (const float4*)(vl + (size_t)row * DCONST);
    float4 v = vp[t];
    float ss = v.x * v.x + v.y * v.y + v.z * v.z + v.w * v.w;
    #pragma unroll
    for (int off = 16; off; off >>= 1)
        ss += __shfl_xor_sync(0xffffffffu, ss, off);
    __shared__ float sw[4];
    __shared__ float s_rinv;
    int w = t >> 5;
    if ((t & 31) == 0) sw[w] = ss;
    __syncthreads();
    if (t == 0)
        s_rinv = 1.f / fmaxf(sqrtf(sw[0] + sw[1] + sw[2] + sw[3]), EPSF);
    __syncthreads();
    float rv = s_rinv;
    __nv_bfloat162 lo = __floats2bfloat162_rn(v.x * rv, v.y * rv);
    __nv_bfloat162 hi = __floats2bfloat162_rn(v.z * rv, v.w * rv);
    uint2 pk;
    pk.x = *(uint32_t*)&lo;
    pk.y = *(uint32_t*)&hi;
    *(uint2*)(g_vbf + (size_t)row * DCONST + t * 4) = pk;
}

// ---------------- K3: HMMA GEMM (128x256 tile, 8 warps of 64x64) + fused top-2 ----------------
__device__ __forceinline__ void load_stage(uint32_t stA, uint32_t stB,
                                           const char* Asrc, const char* Bsrc,
                                           const uint32_t (&dstA)[2],
                                           const uint32_t (&dstB)[4]) {
    // 256 threads: A 512 cp16 (2/thread), B 1024 cp16 (4/thread)
    #pragma unroll
    for (int i = 0; i < 2; i++)
        cp16(stA + dstA[i], Asrc + (size_t)i * 64 * 1024);
    #pragma unroll
    for (int i = 0; i < 4; i++)
        cp16(stB + dstB[i], Bsrc + (size_t)i * 64 * 1024);
    CP_COMMIT();
}

__global__ void __launch_bounds__(256) k_gemm_mma() {
    extern __shared__ char dsm[];
    const int tid = threadIdx.x;     // 256
    const int wid = tid >> 5;        // 0..7
    const int lane = tid & 31;

    const uint32_t base = smem_u32(dsm);
    const int rowBase = blockIdx.x * BM;
    const int colBase = blockIdx.y * BN;

    // ---- load-stage addressing (per-thread, loop-invariant) ----
    const uint32_t lr0 = (uint32_t)(tid >> 2);       // 0..63
    const uint32_t lc0 = (uint32_t)(tid & 3);
    uint32_t dstA[2], dstB[4];
    #pragma unroll
    for (int i = 0; i < 4; i++) {
        uint32_t r = lr0 + (uint32_t)(i * 64);
        uint32_t d = r * 64u + ((lc0 ^ swz(r)) << 4);
        if (i < 2) dstA[i] = d;
        dstB[i] = d;
    }
    const char* Asrc0 = (const char*)(g_abf + (size_t)(rowBase + lr0) * DCONST) + lc0 * 16;
    const char* Bsrc0 = (const char*)(g_vbf + (size_t)(colBase + lr0) * DCONST) + lc0 * 16;

    const int wm = (wid & 1) * 64;   // warp M offset (2 M-groups)
    const int wn = (wid >> 1) * 64;  // warp N offset (4 N-groups)

    float acc[4][8][4];
    #pragma unroll
    for (int mt = 0; mt < 4; mt++)
        #pragma unroll
        for (int nt = 0; nt < 8; nt++)
            #pragma unroll
            for (int e = 0; e < 4; e++) acc[mt][nt][e] = 0.f;

    // ---- hoisted ldmatrix fragment offsets (within a stage) ----
    const uint32_t arow0 = (uint32_t)(wm + (lane & 15));                      // + mt*16
    const uint32_t achk  = (uint32_t)(lane >> 4);                             // 0/1
    const uint32_t brow0 = (uint32_t)(wn + (lane & 7) + ((lane >> 4) << 3));  // + ng*16
    const uint32_t bchk  = (uint32_t)((lane >> 3) & 1);

    uint32_t offA[2][4];   // [ks][mt]
    uint32_t offB[2][4];   // [ks][ng]
    #pragma unroll
    for (int ks = 0; ks < 2; ks++) {
        #pragma unroll
        for (int mt = 0; mt < 4; mt++) {
            uint32_t rr = arow0 + (uint32_t)(mt * 16);
            uint32_t c = (uint32_t)(ks * 2) + achk;
            offA[ks][mt] = rr * 64u + ((c ^ swz(rr)) << 4);
        }
        #pragma unroll
        for (int ng = 0; ng < 4; ng++) {
            uint32_t nn = brow0 + (uint32_t)(ng * 16);
            uint32_t c = (uint32_t)(ks * 2) + bchk;
            offB[ks][ng] = (uint32_t)A_BYTES + nn * 64u + ((c ^ swz(nn)) << 4);
        }
    }

    // Prologue: stages 0,1
    load_stage(base, base + A_BYTES, Asrc0, Bsrc0, dstA, dstB);
    load_stage(base + STAGE_BYTES, base + STAGE_BYTES + A_BYTES,
               Asrc0 + 64, Bsrc0 + 64, dstA, dstB);

    #pragma unroll 1
    for (int kc = 0; kc < NKC; kc++) {
        if (kc + 1 < NKC) { CP_WAIT(1); } else { CP_WAIT(0); }  // tail: drain fully
        __syncthreads();
        if (kc + 2 < NKC) {
            uint32_t slot = base + (uint32_t)((kc + 2) % STAGES) * STAGE_BYTES;
            load_stage(slot, slot + A_BYTES,
                       Asrc0 + (kc + 2) * 64, Bsrc0 + (kc + 2) * 64, dstA, dstB);
        }
        const uint32_t st = base + (uint32_t)(kc % STAGES) * STAGE_BYTES;

        #pragma unroll
        for (int ks = 0; ks < 2; ks++) {
            uint32_t a[4][4];
            #pragma unroll
            for (int mt = 0; mt < 4; mt++)
                ldsm4(a[mt], st + offA[ks][mt]);
            uint32_t b[4][4];
            #pragma unroll
            for (int ng = 0; ng < 4; ng++)
                ldsm4(b[ng], st + offB[ks][ng]);
            #pragma unroll
            for (int mt = 0; mt < 4; mt++)
                #pragma unroll
                for (int nt = 0; nt < 8; nt++)
                    mma16816(acc[mt][nt], a[mt], b[nt >> 1][(nt & 1) * 2],
                             b[nt >> 1][(nt & 1) * 2 + 1]);
        }
        __syncthreads();
    }

    // ---- Epilogue: per-row top-2 over the CTA's 256 cols ----
    // Reuse dead stage smem (drained by the loop's final barrier).
    float* sm1 = (float*)dsm;          // [4][128]
    float* sm2 = sm1 + 512;            // [4][128]
    int*   si1 = (int*)(sm2 + 512);    // [4][128]

    const int ngrp = wid >> 1;         // which 64-col group (0..3)
    #pragma unroll
    for (int mt = 0; mt < 4; mt++) {
        #pragma unroll
        for (int h = 0; h < 2; h++) {
            float m1 = -3.f, m2 = -3.f;
            int i1 = 0x7fffffff;
            #pragma unroll
            for (int nt = 0; nt < 8; nt++) {
                #pragma unroll
                for (int j = 0; j < 2; j++) {
                    int gc = colBase + wn + nt * 8 + (lane & 3) * 2 + j;
                    float v = acc[mt][nt][h * 2 + j];
                    if (gc < VQ) {
                        if (v > m1) { m2 = m1; m1 = v; i1 = gc; }
                        else if (v > m2) m2 = v;
                    }
                }
            }
            #pragma unroll
            for (int off = 1; off < 4; off <<= 1) {
                float o1 = __shfl_xor_sync(0xffffffffu, m1, off);
                int   oi = __shfl_xor_sync(0xffffffffu, i1, off);
                float o2 = __shfl_xor_sync(0xffffffffu, m2, off);
                merge_top2(m1, i1, m2, o1, oi, o2);
            }
            if ((lane & 3) == 0) {
                int rl = wm + mt * 16 + (lane >> 2) + h * 8;   // 0..127
                sm1[ngrp * 128 + rl] = m1;
                sm2[ngrp * 128 + rl] = m2;
                si1[ngrp * 128 + rl] = i1;
            }
        }
    }
    __syncthreads();
    if (tid < 128) {
        float m1 = sm1[tid], m2 = sm2[tid];
        int i1 = si1[tid];
        #pragma unroll
        for (int g = 1; g < 4; g++)
            merge_top2(m1, i1, m2, sm1[g * 128 + tid], si1[g * 128 + tid],
                       sm2[g * 128 + tid]);
        g_part[(size_t)(rowBase + tid) * NCT + blockIdx.y] =
            make_float4(m1, m2, __int_as_float(i1), 0.f);
    }
}

// ---------------- K4: merge partials, vec0==target check, per-row cost ----------------
__global__ void k_finalize(const float* __restrict__ vl,
                           const float* __restrict__ tgt) {
    const int row = blockIdx.x;
    const int tid = threadIdx.x;   // 128
    float m1 = -3.f, m2 = -3.f;
    int i1 = 0x7fffffff;
    for (int t = tid; t < NCT; t += 128) {
        float4 p = g_part[(size_t)row * NCT + t];
        merge_top2(m1, i1, m2, p.x, __float_as_int(p.z), p.y);
    }
    __shared__ float sm1[128], sm2[128];
    __shared__ int   si[128];
    __shared__ float fs1, fs2;
    __shared__ int   fi1, eqflag;
    sm1[tid] = m1; sm2[tid] = m2; si[tid] = i1;
    __syncthreads();
    if (tid == 0) {
        float a1 = sm1[0], a2 = sm2[0];
        int ai = si[0];
        for (int t = 1; t < 128; t++)
            merge_top2(a1, ai, a2, sm1[t], si[t], sm2[t]);
        fs1 = a1; fs2 = a2; fi1 = ai; eqflag = 1;
    }
    __syncthreads();
    {   // exact elementwise equality: veclist[top1] == target[row]
        const float4* vp = (const float4*)(vl + (size_t)fi1 * DCONST);
        const float4* tp = (const float4*)(tgt + (size_t)row * DCONST);
        float4 a = vp[tid];
        float4 b = tp[tid];
        if (a.x != b.x || a.y != b.y || a.z != b.z || a.w != b.w)
            eqflag = 0;   // benign race: only 0 is written
    }
    __syncthreads();
    if (tid == 0) {
        float s = eqflag ? fs2 : fs1;
        float dneg = sqrtf(fmaxf(2.f * (1.f - s), 1e-12f));
        float margin = 0.5f + g_dpos[row] - dneg;   // GAMMA = 0.5
        g_rowcost[row] = 2.f * fmaxf(margin, 0.f);  // RANK = 2
    }
}

// ---------------- K5: deterministic final reduce ----------------
__global__ void k_reduce(float* __restrict__ out, int B) {
    __shared__ float s[1024];
    int t = threadIdx.x;
    float v = 0.f;
    for (int i = t; i < B; i += 1024) v += g_rowcost[i];
    s[t] = v;
    __syncthreads();
    #pragma unroll
    for (int off = 512; off; off >>= 1) {
        if (t < off) s[t] += s[t + off];
        __syncthreads();
    }
    if (t == 0) out[0] = s[0] / (float)B;
}

extern "C" void kernel_launch(void* const* d_in, const int* in_sizes, int n_in,
                              void* d_out, int out_size) {
    const float* inp = (const float*)d_in[0];
    const float* tgt = (const float*)d_in[1];
    const float* vl  = (const float*)d_in[2];

    // Idempotent attribute set (non-stream API; capture-safe, no allocation)
    cudaFuncSetAttribute(k_gemm_mma, cudaFuncAttributeMaxDynamicSharedMemorySize,
                         GEMM_DSMEM);

    k_rowstats_cvt<<<BQ, 128>>>(inp, tgt);
    k_cvt_v<<<VPAD, 128>>>(vl);
    dim3 g3(BQ / BM, NCT);   // row tiles fast-varying -> B col-tile reuse in L2
    k_gemm_mma<<<g3, 256, GEMM_DSMEM>>>();
    k_finalize<<<BQ, 128>>>(vl, tgt);
    k_reduce<<<1, 1024>>>((float*)d_out, BQ);
}

// round 15
// speedup vs baseline: 1.5240x; 1.5240x over previous
#include <cuda_runtime.h>
#include <cuda_bf16.h>
#include <math.h>
#include <stdint.h>

// Geometry (fixed): B=4096, D=512, V=50000
#define DCONST 512
#define BQ     4096
#define VQ     50000
#define NCT    391            // ceil(50000/128)
#define VPAD   (NCT * 128)    // 50048
#define BM     128
#define BN     128
#define BK     32             // bf16 -> 64 bytes per row-chunk
#define NKC    (DCONST / BK)  // 16 k-chunks
#define STAGES 4
#define STAGE_BYTES 16384     // A 8KB + B 8KB
#define GEMM_DSMEM (STAGES * STAGE_BYTES)   // 65536 (opt-in; 2 CTAs = 128KB/SM)
#define EPSF   1e-8f

// ---------------- scratch (device globals) ----------------
__device__ __align__(128) __nv_bfloat16 g_abf[(size_t)BQ * DCONST];    // 4 MB
__device__ __align__(128) __nv_bfloat16 g_vbf[(size_t)VPAD * DCONST];  // 51.2 MB
__device__ float  g_dpos[BQ];
__device__ float4 g_part[(size_t)BQ * NCT];
__device__ float  g_rowcost[BQ];

// ---------------- PTX helpers ----------------
__device__ __forceinline__ uint32_t smem_u32(const void* p) {
    uint32_t a;
    asm("{ .reg .u64 t; cvta.to.shared.u64 t, %1; cvt.u32.u64 %0, t; }" : "=r"(a) : "l"(p));
    return a;
}
__device__ __forceinline__ void cp16(uint32_t dst, const void* src) {
    asm volatile("cp.async.cg.shared.global [%0], [%1], 16;" :: "r"(dst), "l"(src) : "memory");
}
#define CP_COMMIT() asm volatile("cp.async.commit_group;" ::: "memory")
#define CP_WAIT(n)  asm volatile("cp.async.wait_group %0;" :: "n"(n) : "memory")

__device__ __forceinline__ void ldsm4(uint32_t (&r)[4], uint32_t addr) {
    asm volatile("ldmatrix.sync.aligned.m8n8.x4.shared.b16 {%0,%1,%2,%3}, [%4];"
        : "=r"(r[0]), "=r"(r[1]), "=r"(r[2]), "=r"(r[3]) : "r"(addr));
}
__device__ __forceinline__ void mma16816(float (&d)[4], const uint32_t (&a)[4],
                                         uint32_t b0, uint32_t b1) {
    asm volatile(
        "mma.sync.aligned.m16n8k16.row.col.f32.bf16.bf16.f32 "
        "{%0,%1,%2,%3}, {%4,%5,%6,%7}, {%8,%9}, {%0,%1,%2,%3};"
        : "+f"(d[0]), "+f"(d[1]), "+f"(d[2]), "+f"(d[3])
        : "r"(a[0]), "r"(a[1]), "r"(a[2]), "r"(a[3]), "r"(b0), "r"(b1));
}

// XOR swizzle of 16B chunk index within a 64B row (conflict-free for both
// cp.async stores and ldmatrix 8-lane phases)
__device__ __forceinline__ uint32_t swz(uint32_t r) {
    return (r & 3u) ^ ((r >> 2) & 1u);
}

// Top-2 merge, lower index wins ties (matches lax.top_k)
__device__ __forceinline__ void merge_top2(float &m1, int &i1, float &m2,
                                           float o1, int oi, float o2) {
    if (o1 > m1 || (o1 == m1 && oi < i1)) {
        m2 = fmaxf(m1, o2);
        m1 = o1;
        i1 = oi;
    } else {
        m2 = fmaxf(m2, o1);
    }
}

// ---------------- K1: row stats (d_pos) + normalized bf16 input ----------------
__global__ void k_rowstats_cvt(const float* __restrict__ inp,
                               const float* __restrict__ tgt) {
    const int row = blockIdx.x;
    const int t = threadIdx.x;  // 128
    const float4* ip = (const float4*)(inp + (size_t)row * DCONST);
    const float4* tp = (const float4*)(tgt + (size_t)row * DCONST);
    float4 a = ip[t];
    float4 b = tp[t];
    float ssi = a.x * a.x + a.y * a.y + a.z * a.z + a.w * a.w;
    float sst = b.x * b.x + b.y * b.y + b.z * b.z + b.w * b.w;
    float dot = a.x * b.x + a.y * b.y + a.z * b.z + a.w * b.w;
    #pragma unroll
    for (int off = 16; off; off >>= 1) {
        ssi += __shfl_xor_sync(0xffffffffu, ssi, off);
        sst += __shfl_xor_sync(0xffffffffu, sst, off);
        dot += __shfl_xor_sync(0xffffffffu, dot, off);
    }
    __shared__ float s1[4], s2[4], s3[4];
    __shared__ float s_rinv;
    int w = t >> 5;
    if ((t & 31) == 0) { s1[w] = ssi; s2[w] = sst; s3[w] = dot; }
    __syncthreads();
    if (t == 0) {
        float si = s1[0] + s1[1] + s1[2] + s1[3];
        float st = s2[0] + s2[1] + s2[2] + s2[3];
        float dd = s3[0] + s3[1] + s3[2] + s3[3];
        float ni = fmaxf(sqrtf(si), EPSF);
        float nt = fmaxf(sqrtf(st), EPSF);
        float sim = dd / (ni * nt);
        g_dpos[row] = sqrtf(fmaxf(2.f * (1.f - sim), 1e-12f));
        s_rinv = 1.f / ni;
    }
    __syncthreads();
    float rv = s_rinv;
    __nv_bfloat162 lo = __floats2bfloat162_rn(a.x * rv, a.y * rv);
    __nv_bfloat162 hi = __floats2bfloat162_rn(a.z * rv, a.w * rv);
    uint2 pk;
    pk.x = *(uint32_t*)&lo;
    pk.y = *(uint32_t*)&hi;
    *(uint2*)(g_abf + (size_t)row * DCONST + t * 4) = pk;
}

// ---------------- K2: normalized bf16 veclist (zero-padded to VPAD) ----------------
__global__ void k_cvt_v(const float* __restrict__ vl) {
    const int row = blockIdx.x;
    const int t = threadIdx.x;  // 128
    if (row >= VQ) {
        *(uint2*)(g_vbf + (size_t)row * DCONST + t * 4) = make_uint2(0u, 0u);
        return;
    }
    const float4* vp = (const float4*)(vl + (size_t)row * DCONST);
    float4 v = vp[t];
    float ss = v.x * v.x + v.y * v.y + v.z * v.z + v.w * v.w;
    #pragma unroll
    for (int off = 16; off; off >>= 1)
        ss += __shfl_xor_sync(0xffffffffu, ss, off);
    __shared__ float sw[4];
    __shared__ float s_rinv;
    int w = t >> 5;
    if ((t & 31) == 0) sw[w] = ss;
    __syncthreads();
    if (t == 0)
        s_rinv = 1.f / fmaxf(sqrtf(sw[0] + sw[1] + sw[2] + sw[3]), EPSF);
    __syncthreads();
    float rv = s_rinv;
    __nv_bfloat162 lo = __floats2bfloat162_rn(v.x * rv, v.y * rv);
    __nv_bfloat162 hi = __floats2bfloat162_rn(v.z * rv, v.w * rv);
    uint2 pk;
    pk.x = *(uint32_t*)&lo;
    pk.y = *(uint32_t*)&hi;
    *(uint2*)(g_vbf + (size_t)row * DCONST + t * 4) = pk;
}

// ---------------- K3: HMMA GEMM (128x128 tile, 4 warps of 64x64) + fused top-2 ----------------
__device__ __forceinline__ void load_stage(uint32_t stA, uint32_t stB,
                                           const char* Asrc, const char* Bsrc,
                                           const uint32_t (&dst)[4]) {
    // 128 threads x 8 cp16 = 1024 cp16 = 16KB (A 8KB + B 8KB)
    #pragma unroll
    for (int i = 0; i < 4; i++) {
        cp16(stA + dst[i], Asrc + (size_t)i * 32 * 1024);
        cp16(stB + dst[i], Bsrc + (size_t)i * 32 * 1024);
    }
    CP_COMMIT();
}

__global__ void __launch_bounds__(128) k_gemm_mma() {
    extern __shared__ char dsm[];
    const int tid = threadIdx.x;     // 128
    const int wid = tid >> 5;        // 0..3
    const int lane = tid & 31;

    const uint32_t base = smem_u32(dsm);
    const int rowBase = blockIdx.x * BM;
    const int colBase = blockIdx.y * BN;

    // ---- load-stage addressing (per-thread, loop-invariant) ----
    const uint32_t lr0 = (uint32_t)(tid >> 2);       // 0..31
    const uint32_t lc0 = (uint32_t)(tid & 3);
    uint32_t ldst[4];
    #pragma unroll
    for (int i = 0; i < 4; i++) {
        uint32_t r = lr0 + (uint32_t)(i * 32);
        ldst[i] = r * 64u + ((lc0 ^ swz(r)) << 4);
    }
    const char* Asrc0 = (const char*)(g_abf + (size_t)(rowBase + lr0) * DCONST) + lc0 * 16;
    const char* Bsrc0 = (const char*)(g_vbf + (size_t)(colBase + lr0) * DCONST) + lc0 * 16;

    const int wm = (wid & 1) * 64;   // warp M offset (2 M-warps, 64 rows)
    const int wn = (wid >> 1) * 64;  // warp N offset (2 N-warps, 64 cols)

    float acc[4][8][4];
    #pragma unroll
    for (int mt = 0; mt < 4; mt++)
        #pragma unroll
        for (int nt = 0; nt < 8; nt++)
            #pragma unroll
            for (int e = 0; e < 4; e++) acc[mt][nt][e] = 0.f;

    // ---- hoisted ldmatrix fragment offsets (within a stage) ----
    const uint32_t arow0 = (uint32_t)(wm + (lane & 15));                      // + mt*16
    const uint32_t achk  = (uint32_t)(lane >> 4);                             // 0/1
    const uint32_t brow0 = (uint32_t)(wn + (lane & 7) + ((lane >> 4) << 3));  // + ng*16
    const uint32_t bchk  = (uint32_t)((lane >> 3) & 1);

    uint32_t offA[2][4];   // [ks][mt]
    uint32_t offB[2][4];   // [ks][ng]
    #pragma unroll
    for (int ks = 0; ks < 2; ks++) {
        #pragma unroll
        for (int mt = 0; mt < 4; mt++) {
            uint32_t rr = arow0 + (uint32_t)(mt * 16);
            uint32_t c = (uint32_t)(ks * 2) + achk;
            offA[ks][mt] = rr * 64u + ((c ^ swz(rr)) << 4);
        }
        #pragma unroll
        for (int ng = 0; ng < 4; ng++) {
            uint32_t nn = brow0 + (uint32_t)(ng * 16);
            uint32_t c = (uint32_t)(ks * 2) + bchk;
            offB[ks][ng] = 8192u + nn * 64u + ((c ^ swz(nn)) << 4);
        }
    }

    // Prologue: stages 0,1,2 (prefetch distance 3)
    load_stage(base, base + 8192u, Asrc0, Bsrc0, ldst);
    load_stage(base + STAGE_BYTES, base + STAGE_BYTES + 8192u,
               Asrc0 + 64, Bsrc0 + 64, ldst);
    load_stage(base + 2 * STAGE_BYTES, base + 2 * STAGE_BYTES + 8192u,
               Asrc0 + 128, Bsrc0 + 128, ldst);

    #pragma unroll 1
    for (int kc = 0; kc < NKC; kc++) {
        // Tiered wait: ensure group kc complete (groups retire in order)
        if (kc + 2 < NKC)      { CP_WAIT(2); }
        else if (kc + 1 < NKC) { CP_WAIT(1); }
        else                   { CP_WAIT(0); }
        __syncthreads();   // single barrier per kc (dist-3: slot kc%4's next
                           // writer is iter kc+1's prefetch, behind kc+1's barrier)
        const uint32_t st = base + (uint32_t)(kc % STAGES) * STAGE_BYTES;

        // ---- ks = 0 compute first (critical path right after barrier) ----
        {
            uint32_t a[4][4];
            #pragma unroll
            for (int mt = 0; mt < 4; mt++)
                ldsm4(a[mt], st + offA[0][mt]);
            uint32_t b[4][4];
            #pragma unroll
            for (int ng = 0; ng < 4; ng++)
                ldsm4(b[ng], st + offB[0][ng]);
            #pragma unroll
            for (int mt = 0; mt < 4; mt++)
                #pragma unroll
                for (int nt = 0; nt < 8; nt++)
                    mma16816(acc[mt][nt], a[mt], b[nt >> 1][(nt & 1) * 2],
                             b[nt >> 1][(nt & 1) * 2 + 1]);
        }
        // ---- prefetch kc+3 (issue overlapped under compute) ----
        if (kc + 3 < NKC) {
            uint32_t slot = base + (uint32_t)((kc + 3) % STAGES) * STAGE_BYTES;
            load_stage(slot, slot + 8192u,
                       Asrc0 + (kc + 3) * 64, Bsrc0 + (kc + 3) * 64, ldst);
        }
        // ---- ks = 1 compute ----
        {
            uint32_t a[4][4];
            #pragma unroll
            for (int mt = 0; mt < 4; mt++)
                ldsm4(a[mt], st + offA[1][mt]);
            uint32_t b[4][4];
            #pragma unroll
            for (int ng = 0; ng < 4; ng++)
                ldsm4(b[ng], st + offB[1][ng]);
            #pragma unroll
            for (int mt = 0; mt < 4; mt++)
                #pragma unroll
                for (int nt = 0; nt < 8; nt++)
                    mma16816(acc[mt][nt], a[mt], b[nt >> 1][(nt & 1) * 2],
                             b[nt >> 1][(nt & 1) * 2 + 1]);
        }
        // no trailing barrier (safe per dist-3 argument above)
    }
    __syncthreads();   // protect epilogue smem reuse below

    // ---- Epilogue: per-row top-2 over the CTA's 128 cols ----
    float* sm1 = (float*)dsm;          // [2][128]
    float* sm2 = sm1 + 256;            // [2][128]
    int*   si1 = (int*)(sm2 + 256);    // [2][128]

    const int nhalf = wid >> 1;        // which 64-col half
    #pragma unroll
    for (int mt = 0; mt < 4; mt++) {
        #pragma unroll
        for (int h = 0; h < 2; h++) {
            float m1 = -3.f, m2 = -3.f;
            int i1 = 0x7fffffff;
            #pragma unroll
            for (int nt = 0; nt < 8; nt++) {
                #pragma unroll
                for (int j = 0; j < 2; j++) {
                    int gc = colBase + wn + nt * 8 + (lane & 3) * 2 + j;
                    float v = acc[mt][nt][h * 2 + j];
                    if (gc < VQ) {
                        if (v > m1) { m2 = m1; m1 = v; i1 = gc; }
                        else if (v > m2) m2 = v;
                    }
                }
            }
            #pragma unroll
            for (int off = 1; off < 4; off <<= 1) {
                float o1 = __shfl_xor_sync(0xffffffffu, m1, off);
                int   oi = __shfl_xor_sync(0xffffffffu, i1, off);
                float o2 = __shfl_xor_sync(0xffffffffu, m2, off);
                merge_top2(m1, i1, m2, o1, oi, o2);
            }
            if ((lane & 3) == 0) {
                int rl = wm + mt * 16 + (lane >> 2) + h * 8;   // 0..127
                sm1[nhalf * 128 + rl] = m1;
                sm2[nhalf * 128 + rl] = m2;
                si1[nhalf * 128 + rl] = i1;
            }
        }
    }
    __syncthreads();
    {
        float m1 = sm1[tid], m2 = sm2[tid];
        int i1 = si1[tid];
        merge_top2(m1, i1, m2, sm1[128 + tid], si1[128 + tid], sm2[128 + tid]);
        g_part[(size_t)(rowBase + tid) * NCT + blockIdx.y] =
            make_float4(m1, m2, __int_as_float(i1), 0.f);
    }
}

// ---------------- K4: merge partials, vec0==target check, per-row cost ----------------
__global__ void k_finalize(const float* __restrict__ vl,
                           const float* __restrict__ tgt) {
    const int row = blockIdx.x;
    const int tid = threadIdx.x;   // 128
    float m1 = -3.f, m2 = -3.f;
    int i1 = 0x7fffffff;
    for (int t = tid; t < NCT; t += 128) {
        float4 p = g_part[(size_t)row * NCT + t];
        merge_top2(m1, i1, m2, p.x, __float_as_int(p.z), p.y);
    }
    __shared__ float sm1[128], sm2[128];
    __shared__ int   si[128];
    __shared__ float fs1, fs2;
    __shared__ int   fi1, eqflag;
    sm1[tid] = m1; sm2[tid] = m2; si[tid] = i1;
    __syncthreads();
    if (tid == 0) {
        float a1 = sm1[0], a2 = sm2[0];
        int ai = si[0];
        for (int t = 1; t < 128; t++)
            merge_top2(a1, ai, a2, sm1[t], si[t], sm2[t]);
        fs1 = a1; fs2 = a2; fi1 = ai; eqflag = 1;
    }
    __syncthreads();
    {   // exact elementwise equality: veclist[top1] == target[row]
        const float4* vp = (const float4*)(vl + (size_t)fi1 * DCONST);
        const float4* tp = (const float4*)(tgt + (size_t)row * DCONST);
        float4 a = vp[tid];
        float4 b = tp[tid];
        if (a.x != b.x || a.y != b.y || a.z != b.z || a.w != b.w)
            eqflag = 0;   // benign race: only 0 is written
    }
    __syncthreads();
    if (tid == 0) {
        float s = eqflag ? fs2 : fs1;
        float dneg = sqrtf(fmaxf(2.f * (1.f - s), 1e-12f));
        float margin = 0.5f + g_dpos[row] - dneg;   // GAMMA = 0.5
        g_rowcost[row] = 2.f * fmaxf(margin, 0.f);  // RANK = 2
    }
}

// ---------------- K5: deterministic final reduce ----------------
__global__ void k_reduce(float* __restrict__ out, int B) {
    __shared__ float s[1024];
    int t = threadIdx.x;
    float v = 0.f;
    for (int i = t; i < B; i += 1024) v += g_rowcost[i];
    s[t] = v;
    __syncthreads();
    #pragma unroll
    for (int off = 512; off; off >>= 1) {
        if (t < off) s[t] += s[t + off];
        __syncthreads();
    }
    if (t == 0) out[0] = s[0] / (float)B;
}

extern "C" void kernel_launch(void* const* d_in, const int* in_sizes, int n_in,
                              void* d_out, int out_size) {
    const float* inp = (const float*)d_in[0];
    const float* tgt = (const float*)d_in[1];
    const float* vl  = (const float*)d_in[2];

    // Idempotent attribute set (non-stream API; capture-safe, no allocation)
    cudaFuncSetAttribute(k_gemm_mma, cudaFuncAttributeMaxDynamicSharedMemorySize,
                         GEMM_DSMEM);

    k_rowstats_cvt<<<BQ, 128>>>(inp, tgt);
    k_cvt_v<<<VPAD, 128>>>(vl);
    dim3 g3(BQ / BM, NCT);   // row tiles fast-varying -> B col-tile reuse in L2
    k_gemm_mma<<<g3, 128, GEMM_DSMEM>>>();
    k_finalize<<<BQ, 128>>>(vl, tgt);
    k_reduce<<<1, 1024>>>((float*)d_out, BQ);
}

// round 16
// speedup vs baseline: 1.5396x; 1.0102x over previous
#include <cuda_runtime.h>
#include <cuda_bf16.h>
#include <math.h>
#include <stdint.h>

// Geometry (fixed): B=4096, D=512, V=50000
#define DCONST 512
#define BQ     4096
#define VQ     50000
#define NCT    391            // ceil(50000/128)
#define VPAD   (NCT * 128)    // 50048
#define BM     128
#define BN     128
#define BK     32             // bf16 -> 64 bytes per row-chunk
#define NKC    (DCONST / BK)  // 16 k-chunks
#define STAGES 4
#define STAGE_BYTES 16384     // A 8KB + B 8KB
#define GEMM_DSMEM (STAGES * STAGE_BYTES)   // 65536 (opt-in; 2 CTAs = 128KB/SM)
#define EPSF   1e-8f

// ---------------- scratch (device globals) ----------------
__device__ __align__(128) __nv_bfloat16 g_abf[(size_t)BQ * DCONST];    // 4 MB
__device__ __align__(128) __nv_bfloat16 g_vbf[(size_t)VPAD * DCONST];  // 51.2 MB
__device__ float  g_dpos[BQ];
__device__ float4 g_part[(size_t)BQ * NCT];
__device__ float  g_rowcost[BQ];

// ---------------- PTX helpers ----------------
__device__ __forceinline__ uint32_t smem_u32(const void* p) {
    uint32_t a;
    asm("{ .reg .u64 t; cvta.to.shared.u64 t, %1; cvt.u32.u64 %0, t; }" : "=r"(a) : "l"(p));
    return a;
}
__device__ __forceinline__ void cp16(uint32_t dst, const void* src) {
    asm volatile("cp.async.cg.shared.global [%0], [%1], 16;" :: "r"(dst), "l"(src) : "memory");
}
#define CP_COMMIT() asm volatile("cp.async.commit_group;" ::: "memory")
#define CP_WAIT(n)  asm volatile("cp.async.wait_group %0;" :: "n"(n) : "memory")

__device__ __forceinline__ void ldsm4(uint32_t (&r)[4], uint32_t addr) {
    asm volatile("ldmatrix.sync.aligned.m8n8.x4.shared.b16 {%0,%1,%2,%3}, [%4];"
        : "=r"(r[0]), "=r"(r[1]), "=r"(r[2]), "=r"(r[3]) : "r"(addr));
}
__device__ __forceinline__ void mma16816(float (&d)[4], const uint32_t (&a)[4],
                                         uint32_t b0, uint32_t b1) {
    asm volatile(
        "mma.sync.aligned.m16n8k16.row.col.f32.bf16.bf16.f32 "
        "{%0,%1,%2,%3}, {%4,%5,%6,%7}, {%8,%9}, {%0,%1,%2,%3};"
        : "+f"(d[0]), "+f"(d[1]), "+f"(d[2]), "+f"(d[3])
        : "r"(a[0]), "r"(a[1]), "r"(a[2]), "r"(a[3]), "r"(b0), "r"(b1));
}

// XOR swizzle of 16B chunk index within a 64B row (conflict-free for both
// cp.async stores and ldmatrix 8-lane phases)
__device__ __forceinline__ uint32_t swz(uint32_t r) {
    return (r & 3u) ^ ((r >> 2) & 1u);
}

// Top-2 merge, lower index wins ties (matches lax.top_k)
__device__ __forceinline__ void merge_top2(float &m1, int &i1, float &m2,
                                           float o1, int oi, float o2) {
    if (o1 > m1 || (o1 == m1 && oi < i1)) {
        m2 = fmaxf(m1, o2);
        m1 = o1;
        i1 = oi;
    } else {
        m2 = fmaxf(m2, o1);
    }
}

// ---------------- K1: fused conversions ----------------
// blocks [0, BQ): row stats (d_pos) + normalized bf16 input
// blocks [BQ, BQ+VPAD): normalized bf16 veclist (zero-padded)
__global__ void k_convert(const float* __restrict__ inp,
                          const float* __restrict__ tgt,
                          const float* __restrict__ vl) {
    const int t = threadIdx.x;  // 128
    if (blockIdx.x < BQ) {
        const int row = blockIdx.x;
        const float4* ip = (const float4*)(inp + (size_t)row * DCONST);
        const float4* tp = (const float4*)(tgt + (size_t)row * DCONST);
        float4 a = ip[t];
        float4 b = tp[t];
        float ssi = a.x * a.x + a.y * a.y + a.z * a.z + a.w * a.w;
        float sst = b.x * b.x + b.y * b.y + b.z * b.z + b.w * b.w;
        float dot = a.x * b.x + a.y * b.y + a.z * b.z + a.w * b.w;
        #pragma unroll
        for (int off = 16; off; off >>= 1) {
            ssi += __shfl_xor_sync(0xffffffffu, ssi, off);
            sst += __shfl_xor_sync(0xffffffffu, sst, off);
            dot += __shfl_xor_sync(0xffffffffu, dot, off);
        }
        __shared__ float s1[4], s2[4], s3[4];
        __shared__ float s_rinv;
        int w = t >> 5;
        if ((t & 31) == 0) { s1[w] = ssi; s2[w] = sst; s3[w] = dot; }
        __syncthreads();
        if (t == 0) {
            float si = s1[0] + s1[1] + s1[2] + s1[3];
            float st = s2[0] + s2[1] + s2[2] + s2[3];
            float dd = s3[0] + s3[1] + s3[2] + s3[3];
            float ni = fmaxf(sqrtf(si), EPSF);
            float nt = fmaxf(sqrtf(st), EPSF);
            float sim = dd / (ni * nt);
            g_dpos[row] = sqrtf(fmaxf(2.f * (1.f - sim), 1e-12f));
            s_rinv = 1.f / ni;
        }
        __syncthreads();
        float rv = s_rinv;
        __nv_bfloat162 lo = __floats2bfloat162_rn(a.x * rv, a.y * rv);
        __nv_bfloat162 hi = __floats2bfloat162_rn(a.z * rv, a.w * rv);
        uint2 pk;
        pk.x = *(uint32_t*)&lo;
        pk.y = *(uint32_t*)&hi;
        *(uint2*)(g_abf + (size_t)row * DCONST + t * 4) = pk;
    } else {
        const int row = blockIdx.x - BQ;
        if (row >= VQ) {
            *(uint2*)(g_vbf + (size_t)row * DCONST + t * 4) = make_uint2(0u, 0u);
            return;
        }
        const float4* vp = (const float4*)(vl + (size_t)row * DCONST);
        float4 v = vp[t];
        float ss = v.x * v.x + v.y * v.y + v.z * v.z + v.w * v.w;
        #pragma unroll
        for (int off = 16; off; off >>= 1)
            ss += __shfl_xor_sync(0xffffffffu, ss, off);
        __shared__ float sw[4];
        __shared__ float s_rinv2;
        int w = t >> 5;
        if ((t & 31) == 0) sw[w] = ss;
        __syncthreads();
        if (t == 0)
            s_rinv2 = 1.f / fmaxf(sqrtf(sw[0] + sw[1] + sw[2] + sw[3]), EPSF);
        __syncthreads();
        float rv = s_rinv2;
        __nv_bfloat162 lo = __floats2bfloat162_rn(v.x * rv, v.y * rv);
        __nv_bfloat162 hi = __floats2bfloat162_rn(v.z * rv, v.w * rv);
        uint2 pk;
        pk.x = *(uint32_t*)&lo;
        pk.y = *(uint32_t*)&hi;
        *(uint2*)(g_vbf + (size_t)row * DCONST + t * 4) = pk;
    }
}

// ---------------- K3: HMMA GEMM (128x128 tile, 4 warps of 64x64) + fused top-2 ----------------
__device__ __forceinline__ void load_stage(uint32_t stA, uint32_t stB,
                                           const char* Asrc, const char* Bsrc,
                                           const uint32_t (&dst)[4]) {
    // 128 threads x 8 cp16 = 1024 cp16 = 16KB (A 8KB + B 8KB)
    #pragma unroll
    for (int i = 0; i < 4; i++) {
        cp16(stA + dst[i], Asrc + (size_t)i * 32 * 1024);
        cp16(stB + dst[i], Bsrc + (size_t)i * 32 * 1024);
    }
    CP_COMMIT();
}

__global__ void __launch_bounds__(128) k_gemm_mma() {
    extern __shared__ char dsm[];
    const int tid = threadIdx.x;     // 128
    const int wid = tid >> 5;        // 0..3
    const int lane = tid & 31;

    const uint32_t base = smem_u32(dsm);
    const int rowBase = blockIdx.x * BM;
    const int colBase = blockIdx.y * BN;

    // ---- load-stage addressing (per-thread, loop-invariant) ----
    const uint32_t lr0 = (uint32_t)(tid >> 2);       // 0..31
    const uint32_t lc0 = (uint32_t)(tid & 3);
    uint32_t ldst[4];
    #pragma unroll
    for (int i = 0; i < 4; i++) {
        uint32_t r = lr0 + (uint32_t)(i * 32);
        ldst[i] = r * 64u + ((lc0 ^ swz(r)) << 4);
    }
    const char* Asrc0 = (const char*)(g_abf + (size_t)(rowBase + lr0) * DCONST) + lc0 * 16;
    const char* Bsrc0 = (const char*)(g_vbf + (size_t)(colBase + lr0) * DCONST) + lc0 * 16;

    const int wm = (wid & 1) * 64;   // warp M offset (2 M-warps, 64 rows)
    const int wn = (wid >> 1) * 64;  // warp N offset (2 N-warps, 64 cols)

    float acc[4][8][4];
    #pragma unroll
    for (int mt = 0; mt < 4; mt++)
        #pragma unroll
        for (int nt = 0; nt < 8; nt++)
            #pragma unroll
            for (int e = 0; e < 4; e++) acc[mt][nt][e] = 0.f;

    // ---- hoisted ldmatrix fragment offsets (within a stage) ----
    const uint32_t arow0 = (uint32_t)(wm + (lane & 15));                      // + mt*16
    const uint32_t achk  = (uint32_t)(lane >> 4);                             // 0/1
    const uint32_t brow0 = (uint32_t)(wn + (lane & 7) + ((lane >> 4) << 3));  // + ng*16
    const uint32_t bchk  = (uint32_t)((lane >> 3) & 1);

    uint32_t offA[2][4];   // [ks][mt]
    uint32_t offB[2][4];   // [ks][ng]
    #pragma unroll
    for (int ks = 0; ks < 2; ks++) {
        #pragma unroll
        for (int mt = 0; mt < 4; mt++) {
            uint32_t rr = arow0 + (uint32_t)(mt * 16);
            uint32_t c = (uint32_t)(ks * 2) + achk;
            offA[ks][mt] = rr * 64u + ((c ^ swz(rr)) << 4);
        }
        #pragma unroll
        for (int ng = 0; ng < 4; ng++) {
            uint32_t nn = brow0 + (uint32_t)(ng * 16);
            uint32_t c = (uint32_t)(ks * 2) + bchk;
            offB[ks][ng] = 8192u + nn * 64u + ((c ^ swz(nn)) << 4);
        }
    }

    // Prologue: stages 0,1,2 (prefetch distance 3)
    load_stage(base, base + 8192u, Asrc0, Bsrc0, ldst);
    load_stage(base + STAGE_BYTES, base + STAGE_BYTES + 8192u,
               Asrc0 + 64, Bsrc0 + 64, ldst);
    load_stage(base + 2 * STAGE_BYTES, base + 2 * STAGE_BYTES + 8192u,
               Asrc0 + 128, Bsrc0 + 128, ldst);

    #pragma unroll 1
    for (int kc = 0; kc < NKC; kc++) {
        // Tiered wait: ensure group kc complete (groups retire in order)
        if (kc + 2 < NKC)      { CP_WAIT(2); }
        else if (kc + 1 < NKC) { CP_WAIT(1); }
        else                   { CP_WAIT(0); }
        __syncthreads();   // single barrier per kc (dist-3: slot kc%4's next
                           // writer is iter kc+1's prefetch, behind kc+1's barrier)
        const uint32_t st = base + (uint32_t)(kc % STAGES) * STAGE_BYTES;

        // ---- ks = 0 compute first (critical path right after barrier) ----
        {
            uint32_t a[4][4];
            #pragma unroll
            for (int mt = 0; mt < 4; mt++)
                ldsm4(a[mt], st + offA[0][mt]);
            uint32_t b[4][4];
            #pragma unroll
            for (int ng = 0; ng < 4; ng++)
                ldsm4(b[ng], st + offB[0][ng]);
            #pragma unroll
            for (int mt = 0; mt < 4; mt++)
                #pragma unroll
                for (int nt = 0; nt < 8; nt++)
                    mma16816(acc[mt][nt], a[mt], b[nt >> 1][(nt & 1) * 2],
                             b[nt >> 1][(nt & 1) * 2 + 1]);
        }
        // ---- prefetch kc+3 (issue overlapped under compute) ----
        if (kc + 3 < NKC) {
            uint32_t slot = base + (uint32_t)((kc + 3) % STAGES) * STAGE_BYTES;
            load_stage(slot, slot + 8192u,
                       Asrc0 + (kc + 3) * 64, Bsrc0 + (kc + 3) * 64, ldst);
        }
        // ---- ks = 1 compute ----
        {
            uint32_t a[4][4];
            #pragma unroll
            for (int mt = 0; mt < 4; mt++)
                ldsm4(a[mt], st + offA[1][mt]);
            uint32_t b[4][4];
            #pragma unroll
            for (int ng = 0; ng < 4; ng++)
                ldsm4(b[ng], st + offB[1][ng]);
            #pragma unroll
            for (int mt = 0; mt < 4; mt++)
                #pragma unroll
                for (int nt = 0; nt < 8; nt++)
                    mma16816(acc[mt][nt], a[mt], b[nt >> 1][(nt & 1) * 2],
                             b[nt >> 1][(nt & 1) * 2 + 1]);
        }
        // no trailing barrier (safe per dist-3 argument above)
    }
    __syncthreads();   // protect epilogue smem reuse below

    // ---- Epilogue: per-row top-2 over the CTA's 128 cols ----
    float* sm1 = (float*)dsm;          // [2][128]
    float* sm2 = sm1 + 256;            // [2][128]
    int*   si1 = (int*)(sm2 + 256);    // [2][128]

    const int nhalf = wid >> 1;        // which 64-col half
    #pragma unroll
    for (int mt = 0; mt < 4; mt++) {
        #pragma unroll
        for (int h = 0; h < 2; h++) {
            float m1 = -3.f, m2 = -3.f;
            int i1 = 0x7fffffff;
            #pragma unroll
            for (int nt = 0; nt < 8; nt++) {
                #pragma unroll
                for (int j = 0; j < 2; j++) {
                    int gc = colBase + wn + nt * 8 + (lane & 3) * 2 + j;
                    float v = acc[mt][nt][h * 2 + j];
                    if (gc < VQ) {
                        if (v > m1) { m2 = m1; m1 = v; i1 = gc; }
                        else if (v > m2) m2 = v;
                    }
                }
            }
            #pragma unroll
            for (int off = 1; off < 4; off <<= 1) {
                float o1 = __shfl_xor_sync(0xffffffffu, m1, off);
                int   oi = __shfl_xor_sync(0xffffffffu, i1, off);
                float o2 = __shfl_xor_sync(0xffffffffu, m2, off);
                merge_top2(m1, i1, m2, o1, oi, o2);
            }
            if ((lane & 3) == 0) {
                int rl = wm + mt * 16 + (lane >> 2) + h * 8;   // 0..127
                sm1[nhalf * 128 + rl] = m1;
                sm2[nhalf * 128 + rl] = m2;
                si1[nhalf * 128 + rl] = i1;
            }
        }
    }
    __syncthreads();
    {
        float m1 = sm1[tid], m2 = sm2[tid];
        int i1 = si1[tid];
        merge_top2(m1, i1, m2, sm1[128 + tid], si1[128 + tid], sm2[128 + tid]);
        g_part[(size_t)(rowBase + tid) * NCT + blockIdx.y] =
            make_float4(m1, m2, __int_as_float(i1), 0.f);
    }
}

// ---------------- K4: merge partials, vec0==target check, per-row cost ----------------
__global__ void k_finalize(const float* __restrict__ vl,
                           const float* __restrict__ tgt) {
    const int row = blockIdx.x;
    const int tid = threadIdx.x;   // 128
    const int lane = tid & 31;
    float m1 = -3.f, m2 = -3.f;
    int i1 = 0x7fffffff;
    for (int t = tid; t < NCT; t += 128) {
        float4 p = g_part[(size_t)row * NCT + t];
        merge_top2(m1, i1, m2, p.x, __float_as_int(p.z), p.y);
    }
    __shared__ float sm1[128], sm2[128];
    __shared__ int   si[128];
    __shared__ float fs1, fs2;
    __shared__ int   fi1, eqflag;
    sm1[tid] = m1; sm2[tid] = m2; si[tid] = i1;
    __syncthreads();
    if (tid < 32) {
        // lane folds entries {tid, tid+32, tid+64, tid+96}, then butterfly
        float a1 = sm1[tid], a2 = sm2[tid];
        int ai = si[tid];
        #pragma unroll
        for (int g = 1; g < 4; g++)
            merge_top2(a1, ai, a2, sm1[g * 32 + tid], si[g * 32 + tid],
                       sm2[g * 32 + tid]);
        #pragma unroll
        for (int off = 16; off; off >>= 1) {
            float o1 = __shfl_xor_sync(0xffffffffu, a1, off);
            int   oi = __shfl_xor_sync(0xffffffffu, ai, off);
            float o2 = __shfl_xor_sync(0xffffffffu, a2, off);
            merge_top2(a1, ai, a2, o1, oi, o2);
        }
        if (lane == 0) { fs1 = a1; fs2 = a2; fi1 = ai; eqflag = 1; }
    }
    __syncthreads();
    {   // exact elementwise equality: veclist[top1] == target[row]
        const float4* vp = (const float4*)(vl + (size_t)fi1 * DCONST);
        const float4* tp = (const float4*)(tgt + (size_t)row * DCONST);
        float4 a = vp[tid];
        float4 b = tp[tid];
        if (a.x != b.x || a.y != b.y || a.z != b.z || a.w != b.w)
            eqflag = 0;   // benign race: only 0 is written
    }
    __syncthreads();
    if (tid == 0) {
        float s = eqflag ? fs2 : fs1;
        float dneg = sqrtf(fmaxf(2.f * (1.f - s), 1e-12f));
        float margin = 0.5f + g_dpos[row] - dneg;   // GAMMA = 0.5
        g_rowcost[row] = 2.f * fmaxf(margin, 0.f);  // RANK = 2
    }
}

// ---------------- K5: deterministic final reduce ----------------
__global__ void k_reduce(float* __restrict__ out, int B) {
    __shared__ float s[1024];
    int t = threadIdx.x;
    float v = 0.f;
    for (int i = t; i < B; i += 1024) v += g_rowcost[i];
    s[t] = v;
    __syncthreads();
    #pragma unroll
    for (int off = 512; off; off >>= 1) {
        if (t < off) s[t] += s[t + off];
        __syncthreads();
    }
    if (t == 0) out[0] = s[0] / (float)B;
}

extern "C" void kernel_launch(void* const* d_in, const int* in_sizes, int n_in,
                              void* d_out, int out_size) {
    const float* inp = (const float*)d_in[0];
    const float* tgt = (const float*)d_in[1];
    const float* vl  = (const float*)d_in[2];

    // Idempotent attribute set (non-stream API; capture-safe, no allocation)
    cudaFuncSetAttribute(k_gemm_mma, cudaFuncAttributeMaxDynamicSharedMemorySize,
                         GEMM_DSMEM);

    k_convert<<<BQ + VPAD, 128>>>(inp, tgt, vl);
    dim3 g3(BQ / BM, NCT);   // row tiles fast-varying -> B col-tile reuse in L2
    k_gemm_mma<<<g3, 128, GEMM_DSMEM>>>();
    k_finalize<<<BQ, 128>>>(vl, tgt);
    k_reduce<<<1, 1024>>>((float*)d_out, BQ);
}

// round 17
// speedup vs baseline: 1.5422x; 1.0016x over previous
#include <cuda_runtime.h>
#include <cuda_bf16.h>
#include <math.h>
#include <stdint.h>

// Geometry (fixed): B=4096, D=512, V=50000
#define DCONST 512
#define BQ     4096
#define VQ     50000
#define NCT    391            // ceil(50000/128)
#define VPAD   (NCT * 128)    // 50048
#define BM     128
#define BN     128
#define BK     32             // bf16 -> 64 bytes per row-chunk
#define NKC    (DCONST / BK)  // 16 k-chunks
#define STAGES 4
#define STAGE_BYTES 16384     // A 8KB + B 8KB
#define GEMM_DSMEM (STAGES * STAGE_BYTES)   // 65536 (opt-in; 2 CTAs = 128KB/SM)
#define EPSF   1e-8f
#define FIXSCALE 17592186044416.0  // 2^44

// ---------------- scratch (device globals) ----------------
__device__ __align__(128) __nv_bfloat16 g_abf[(size_t)BQ * DCONST];    // 4 MB
__device__ __align__(128) __nv_bfloat16 g_vbf[(size_t)VPAD * DCONST];  // 51.2 MB
__device__ float  g_dpos[BQ];
__device__ float4 g_part[(size_t)BQ * NCT];
__device__ unsigned long long g_sum;
__device__ unsigned int g_done;

// ---------------- PTX helpers ----------------
__device__ __forceinline__ uint32_t smem_u32(const void* p) {
    uint32_t a;
    asm("{ .reg .u64 t; cvta.to.shared.u64 t, %1; cvt.u32.u64 %0, t; }" : "=r"(a) : "l"(p));
    return a;
}
__device__ __forceinline__ void cp16(uint32_t dst, const void* src) {
    asm volatile("cp.async.cg.shared.global [%0], [%1], 16;" :: "r"(dst), "l"(src) : "memory");
}
#define CP_COMMIT() asm volatile("cp.async.commit_group;" ::: "memory")
#define CP_WAIT(n)  asm volatile("cp.async.wait_group %0;" :: "n"(n) : "memory")

__device__ __forceinline__ void ldsm4(uint32_t (&r)[4], uint32_t addr) {
    asm volatile("ldmatrix.sync.aligned.m8n8.x4.shared.b16 {%0,%1,%2,%3}, [%4];"
        : "=r"(r[0]), "=r"(r[1]), "=r"(r[2]), "=r"(r[3]) : "r"(addr));
}
__device__ __forceinline__ void mma16816(float (&d)[4], const uint32_t (&a)[4],
                                         uint32_t b0, uint32_t b1) {
    asm volatile(
        "mma.sync.aligned.m16n8k16.row.col.f32.bf16.bf16.f32 "
        "{%0,%1,%2,%3}, {%4,%5,%6,%7}, {%8,%9}, {%0,%1,%2,%3};"
        : "+f"(d[0]), "+f"(d[1]), "+f"(d[2]), "+f"(d[3])
        : "r"(a[0]), "r"(a[1]), "r"(a[2]), "r"(a[3]), "r"(b0), "r"(b1));
}

// XOR swizzle of 16B chunk index within a 64B row (conflict-free for both
// cp.async stores and ldmatrix 8-lane phases)
__device__ __forceinline__ uint32_t swz(uint32_t r) {
    return (r & 3u) ^ ((r >> 2) & 1u);
}

// Top-2 merge, lower index wins ties (matches lax.top_k)
__device__ __forceinline__ void merge_top2(float &m1, int &i1, float &m2,
                                           float o1, int oi, float o2) {
    if (o1 > m1 || (o1 == m1 && oi < i1)) {
        m2 = fmaxf(m1, o2);
        m1 = o1;
        i1 = oi;
    } else {
        m2 = fmaxf(m2, o1);
    }
}

// ---------------- K1: fused conversions (+ accumulator reset) ----------------
// blocks [0, BQ): row stats (d_pos) + normalized bf16 input
// blocks [BQ, BQ+VPAD): normalized bf16 veclist (zero-padded)
__global__ void k_convert(const float* __restrict__ inp,
                          const float* __restrict__ tgt,
                          const float* __restrict__ vl) {
    const int t = threadIdx.x;  // 128
    if (blockIdx.x == 0 && t == 0) { g_sum = 0ull; g_done = 0u; }
    if (blockIdx.x < BQ) {
        const int row = blockIdx.x;
        const float4* ip = (const float4*)(inp + (size_t)row * DCONST);
        const float4* tp = (const float4*)(tgt + (size_t)row * DCONST);
        float4 a = ip[t];
        float4 b = tp[t];
        float ssi = a.x * a.x + a.y * a.y + a.z * a.z + a.w * a.w;
        float sst = b.x * b.x + b.y * b.y + b.z * b.z + b.w * b.w;
        float dot = a.x * b.x + a.y * b.y + a.z * b.z + a.w * b.w;
        #pragma unroll
        for (int off = 16; off; off >>= 1) {
            ssi += __shfl_xor_sync(0xffffffffu, ssi, off);
            sst += __shfl_xor_sync(0xffffffffu, sst, off);
            dot += __shfl_xor_sync(0xffffffffu, dot, off);
        }
        __shared__ float s1[4], s2[4], s3[4];
        __shared__ float s_rinv;
        int w = t >> 5;
        if ((t & 31) == 0) { s1[w] = ssi; s2[w] = sst; s3[w] = dot; }
        __syncthreads();
        if (t == 0) {
            float si = s1[0] + s1[1] + s1[2] + s1[3];
            float st = s2[0] + s2[1] + s2[2] + s2[3];
            float dd = s3[0] + s3[1] + s3[2] + s3[3];
            float ni = fmaxf(sqrtf(si), EPSF);
            float nt = fmaxf(sqrtf(st), EPSF);
            float sim = dd / (ni * nt);
            g_dpos[row] = sqrtf(fmaxf(2.f * (1.f - sim), 1e-12f));
            s_rinv = 1.f / ni;
        }
        __syncthreads();
        float rv = s_rinv;
        __nv_bfloat162 lo = __floats2bfloat162_rn(a.x * rv, a.y * rv);
        __nv_bfloat162 hi = __floats2bfloat162_rn(a.z * rv, a.w * rv);
        uint2 pk;
        pk.x = *(uint32_t*)&lo;
        pk.y = *(uint32_t*)&hi;
        *(uint2*)(g_abf + (size_t)row * DCONST + t * 4) = pk;
    } else {
        const int row = blockIdx.x - BQ;
        if (row >= VQ) {
            *(uint2*)(g_vbf + (size_t)row * DCONST + t * 4) = make_uint2(0u, 0u);
            return;
        }
        const float4* vp = (const float4*)(vl + (size_t)row * DCONST);
        float4 v = vp[t];
        float ss = v.x * v.x + v.y * v.y + v.z * v.z + v.w * v.w;
        #pragma unroll
        for (int off = 16; off; off >>= 1)
            ss += __shfl_xor_sync(0xffffffffu, ss, off);
        __shared__ float sw[4];
        __shared__ float s_rinv2;
        int w = t >> 5;
        if ((t & 31) == 0) sw[w] = ss;
        __syncthreads();
        if (t == 0)
            s_rinv2 = 1.f / fmaxf(sqrtf(sw[0] + sw[1] + sw[2] + sw[3]), EPSF);
        __syncthreads();
        float rv = s_rinv2;
        __nv_bfloat162 lo = __floats2bfloat162_rn(v.x * rv, v.y * rv);
        __nv_bfloat162 hi = __floats2bfloat162_rn(v.z * rv, v.w * rv);
        uint2 pk;
        pk.x = *(uint32_t*)&lo;
        pk.y = *(uint32_t*)&hi;
        *(uint2*)(g_vbf + (size_t)row * DCONST + t * 4) = pk;
    }
}

// ---------------- K3: HMMA GEMM (128x128 tile, 4 warps of 64x64) + fused top-2 ----------------
__device__ __forceinline__ void load_stage(uint32_t stA, uint32_t stB,
                                           const char* Asrc, const char* Bsrc,
                                           const uint32_t (&dst)[4]) {
    // 128 threads x 8 cp16 = 1024 cp16 = 16KB (A 8KB + B 8KB)
    #pragma unroll
    for (int i = 0; i < 4; i++) {
        cp16(stA + dst[i], Asrc + (size_t)i * 32 * 1024);
        cp16(stB + dst[i], Bsrc + (size_t)i * 32 * 1024);
    }
    CP_COMMIT();
}

__global__ void __launch_bounds__(128) k_gemm_mma() {
    extern __shared__ char dsm[];
    const int tid = threadIdx.x;     // 128
    const int wid = tid >> 5;        // 0..3
    const int lane = tid & 31;

    const uint32_t base = smem_u32(dsm);
    const int rowBase = blockIdx.x * BM;
    const int colBase = blockIdx.y * BN;

    // ---- load-stage addressing (per-thread, loop-invariant) ----
    const uint32_t lr0 = (uint32_t)(tid >> 2);       // 0..31
    const uint32_t lc0 = (uint32_t)(tid & 3);
    uint32_t ldst[4];
    #pragma unroll
    for (int i = 0; i < 4; i++) {
        uint32_t r = lr0 + (uint32_t)(i * 32);
        ldst[i] = r * 64u + ((lc0 ^ swz(r)) << 4);
    }
    const char* Asrc0 = (const char*)(g_abf + (size_t)(rowBase + lr0) * DCONST) + lc0 * 16;
    const char* Bsrc0 = (const char*)(g_vbf + (size_t)(colBase + lr0) * DCONST) + lc0 * 16;

    const int wm = (wid & 1) * 64;   // warp M offset (2 M-warps, 64 rows)
    const int wn = (wid >> 1) * 64;  // warp N offset (2 N-warps, 64 cols)

    float acc[4][8][4];
    #pragma unroll
    for (int mt = 0; mt < 4; mt++)
        #pragma unroll
        for (int nt = 0; nt < 8; nt++)
            #pragma unroll
            for (int e = 0; e < 4; e++) acc[mt][nt][e] = 0.f;

    // ---- hoisted ldmatrix fragment offsets (within a stage) ----
    const uint32_t arow0 = (uint32_t)(wm + (lane & 15));                      // + mt*16
    const uint32_t achk  = (uint32_t)(lane >> 4);                             // 0/1
    const uint32_t brow0 = (uint32_t)(wn + (lane & 7) + ((lane >> 4) << 3));  // + ng*16
    const uint32_t bchk  = (uint32_t)((lane >> 3) & 1);

    uint32_t offA[2][4];   // [ks][mt]
    uint32_t offB[2][4];   // [ks][ng]
    #pragma unroll
    for (int ks = 0; ks < 2; ks++) {
        #pragma unroll
        for (int mt = 0; mt < 4; mt++) {
            uint32_t rr = arow0 + (uint32_t)(mt * 16);
            uint32_t c = (uint32_t)(ks * 2) + achk;
            offA[ks][mt] = rr * 64u + ((c ^ swz(rr)) << 4);
        }
        #pragma unroll
        for (int ng = 0; ng < 4; ng++) {
            uint32_t nn = brow0 + (uint32_t)(ng * 16);
            uint32_t c = (uint32_t)(ks * 2) + bchk;
            offB[ks][ng] = 8192u + nn * 64u + ((c ^ swz(nn)) << 4);
        }
    }

    // Prologue: stages 0,1,2 (prefetch distance 3)
    load_stage(base, base + 8192u, Asrc0, Bsrc0, ldst);
    load_stage(base + STAGE_BYTES, base + STAGE_BYTES + 8192u,
               Asrc0 + 64, Bsrc0 + 64, ldst);
    load_stage(base + 2 * STAGE_BYTES, base + 2 * STAGE_BYTES + 8192u,
               Asrc0 + 128, Bsrc0 + 128, ldst);

    #pragma unroll 1
    for (int kc = 0; kc < NKC; kc++) {
        // Tiered wait: ensure group kc complete (groups retire in order)
        if (kc + 2 < NKC)      { CP_WAIT(2); }
        else if (kc + 1 < NKC) { CP_WAIT(1); }
        else                   { CP_WAIT(0); }
        __syncthreads();   // single barrier per kc (dist-3: slot kc%4's next
                           // writer is iter kc+1's prefetch, behind kc+1's barrier)
        const uint32_t st = base + (uint32_t)(kc % STAGES) * STAGE_BYTES;

        // ---- ks = 0 compute first (critical path right after barrier) ----
        {
            uint32_t a[4][4];
            #pragma unroll
            for (int mt = 0; mt < 4; mt++)
                ldsm4(a[mt], st + offA[0][mt]);
            uint32_t b[4][4];
            #pragma unroll
            for (int ng = 0; ng < 4; ng++)
                ldsm4(b[ng], st + offB[0][ng]);
            #pragma unroll
            for (int mt = 0; mt < 4; mt++)
                #pragma unroll
                for (int nt = 0; nt < 8; nt++)
                    mma16816(acc[mt][nt], a[mt], b[nt >> 1][(nt & 1) * 2],
                             b[nt >> 1][(nt & 1) * 2 + 1]);
        }
        // ---- prefetch kc+3 (issue overlapped under compute) ----
        if (kc + 3 < NKC) {
            uint32_t slot = base + (uint32_t)((kc + 3) % STAGES) * STAGE_BYTES;
            load_stage(slot, slot + 8192u,
                       Asrc0 + (kc + 3) * 64, Bsrc0 + (kc + 3) * 64, ldst);
        }
        // ---- ks = 1 compute ----
        {
            uint32_t a[4][4];
            #pragma unroll
            for (int mt = 0; mt < 4; mt++)
                ldsm4(a[mt], st + offA[1][mt]);
            uint32_t b[4][4];
            #pragma unroll
            for (int ng = 0; ng < 4; ng++)
                ldsm4(b[ng], st + offB[1][ng]);
            #pragma unroll
            for (int mt = 0; mt < 4; mt++)
                #pragma unroll
                for (int nt = 0; nt < 8; nt++)
                    mma16816(acc[mt][nt], a[mt], b[nt >> 1][(nt & 1) * 2],
                             b[nt >> 1][(nt & 1) * 2 + 1]);
        }
        // no trailing barrier (safe per dist-3 argument above)
    }
    __syncthreads();   // protect epilogue smem reuse below

    // ---- Epilogue: per-row top-2 over the CTA's 128 cols ----
    float* sm1 = (float*)dsm;          // [2][128]
    float* sm2 = sm1 + 256;            // [2][128]
    int*   si1 = (int*)(sm2 + 256);    // [2][128]

    const int nhalf = wid >> 1;        // which 64-col half
    #pragma unroll
    for (int mt = 0; mt < 4; mt++) {
        #pragma unroll
        for (int h = 0; h < 2; h++) {
            float m1 = -3.f, m2 = -3.f;
            int i1 = 0x7fffffff;
            #pragma unroll
            for (int nt = 0; nt < 8; nt++) {
                #pragma unroll
                for (int j = 0; j < 2; j++) {
                    int gc = colBase + wn + nt * 8 + (lane & 3) * 2 + j;
                    float v = acc[mt][nt][h * 2 + j];
                    if (gc < VQ) {
                        if (v > m1) { m2 = m1; m1 = v; i1 = gc; }
                        else if (v > m2) m2 = v;
                    }
                }
            }
            #pragma unroll
            for (int off = 1; off < 4; off <<= 1) {
                float o1 = __shfl_xor_sync(0xffffffffu, m1, off);
                int   oi = __shfl_xor_sync(0xffffffffu, i1, off);
                float o2 = __shfl_xor_sync(0xffffffffu, m2, off);
                merge_top2(m1, i1, m2, o1, oi, o2);
            }
            if ((lane & 3) == 0) {
                int rl = wm + mt * 16 + (lane >> 2) + h * 8;   // 0..127
                sm1[nhalf * 128 + rl] = m1;
                sm2[nhalf * 128 + rl] = m2;
                si1[nhalf * 128 + rl] = i1;
            }
        }
    }
    __syncthreads();
    {
        float m1 = sm1[tid], m2 = sm2[tid];
        int i1 = si1[tid];
        merge_top2(m1, i1, m2, sm1[128 + tid], si1[128 + tid], sm2[128 + tid]);
        g_part[(size_t)(rowBase + tid) * NCT + blockIdx.y] =
            make_float4(m1, m2, __int_as_float(i1), 0.f);
    }
}

// ---------------- K4: merge partials, eq-check, row cost, fused reduce ----------------
__global__ void k_finalize(const float* __restrict__ vl,
                           const float* __restrict__ tgt,
                           float* __restrict__ out) {
    const int row = blockIdx.x;
    const int tid = threadIdx.x;   // 128
    const int lane = tid & 31;
    float m1 = -3.f, m2 = -3.f;
    int i1 = 0x7fffffff;
    for (int t = tid; t < NCT; t += 128) {
        float4 p = g_part[(size_t)row * NCT + t];
        merge_top2(m1, i1, m2, p.x, __float_as_int(p.z), p.y);
    }
    __shared__ float sm1[128], sm2[128];
    __shared__ int   si[128];
    __shared__ float fs1, fs2;
    __shared__ int   fi1, eqflag;
    sm1[tid] = m1; sm2[tid] = m2; si[tid] = i1;
    __syncthreads();
    if (tid < 32) {
        // lane folds entries {tid, tid+32, tid+64, tid+96}, then butterfly
        float a1 = sm1[tid], a2 = sm2[tid];
        int ai = si[tid];
        #pragma unroll
        for (int g = 1; g < 4; g++)
            merge_top2(a1, ai, a2, sm1[g * 32 + tid], si[g * 32 + tid],
                       sm2[g * 32 + tid]);
        #pragma unroll
        for (int off = 16; off; off >>= 1) {
            float o1 = __shfl_xor_sync(0xffffffffu, a1, off);
            int   oi = __shfl_xor_sync(0xffffffffu, ai, off);
            float o2 = __shfl_xor_sync(0xffffffffu, a2, off);
            merge_top2(a1, ai, a2, o1, oi, o2);
        }
        if (lane == 0) { fs1 = a1; fs2 = a2; fi1 = ai; eqflag = 1; }
    }
    __syncthreads();
    {   // exact elementwise equality: veclist[top1] == target[row]
        const float4* vp = (const float4*)(vl + (size_t)fi1 * DCONST);
        const float4* tp = (const float4*)(tgt + (size_t)row * DCONST);
        float4 a = vp[tid];
        float4 b = tp[tid];
        if (a.x != b.x || a.y != b.y || a.z != b.z || a.w != b.w)
            eqflag = 0;   // benign race: only 0 is written
    }
    __syncthreads();
    if (tid == 0) {
        float s = eqflag ? fs2 : fs1;
        float dneg = sqrtf(fmaxf(2.f * (1.f - s), 1e-12f));
        float margin = 0.5f + g_dpos[row] - dneg;   // GAMMA = 0.5
        float cost = 2.f * fmaxf(margin, 0.f);      // RANK = 2
        // deterministic fixed-point accumulation (integer add is associative)
        unsigned long long q = (unsigned long long)llrintf(cost * (float)FIXSCALE);
        atomicAdd(&g_sum, q);
        __threadfence();
        unsigned int done = atomicAdd(&g_done, 1u);
        if (done == BQ - 1) {
            unsigned long long total = g_sum;   // all adds visible (fence + last)
            out[0] = (float)((double)total / FIXSCALE / (double)BQ);
        }
    }
}

extern "C" void kernel_launch(void* const* d_in, const int* in_sizes, int n_in,
                              void* d_out, int out_size) {
    const float* inp = (const float*)d_in[0];
    const float* tgt = (const float*)d_in[1];
    const float* vl  = (const float*)d_in[2];

    // Idempotent attribute set (non-stream API; capture-safe, no allocation)
    cudaFuncSetAttribute(k_gemm_mma, cudaFuncAttributeMaxDynamicSharedMemorySize,
                         GEMM_DSMEM);

    k_convert<<<BQ + VPAD, 128>>>(inp, tgt, vl);
    dim3 g3(BQ / BM, NCT);   // row tiles fast-varying -> B col-tile reuse in L2
    k_gemm_mma<<<g3, 128, GEMM_DSMEM>>>();
    k_finalize<<<BQ, 128>>>(vl, tgt, (float*)d_out);
}